// round 3
// baseline (speedup 1.0000x reference)
#include <cuda_runtime.h>

#define HID   256
#define LAT   128
#define ODIM  128
#define NBLK  4
#define NIT   10
#define TM    64
#define KC    32
#define NTHR  256
#define SMEM_BYTES ((2 * TM * HID + 2 * KC * HID) * 4)

typedef unsigned long long ull;

__device__ __forceinline__ ull pk2(float lo, float hi) {
    ull r; asm("mov.b64 %0, {%1, %2};" : "=l"(r) : "f"(lo), "f"(hi)); return r;
}
__device__ __forceinline__ void upk2(ull v, float& lo, float& hi) {
    asm("mov.b64 {%0, %1}, %2;" : "=f"(lo), "=f"(hi) : "l"(v));
}
__device__ __forceinline__ void fma2(ull& d, ull a, ull b) {
    asm("fma.rn.f32x2 %0, %1, %2, %0;" : "+l"(d) : "l"(a), "l"(b));
}

// One [TM x HID] = [TM x nk] @ [nk x HID] GEMM with A resident in SMEM (xs),
// weights streamed from global through a double-buffered SMEM chunk (ws).
// mode 0: out = acc + bias
// mode 1: out = relu(acc + bias)
// mode 2: out = ys - (acc + bias)
// Result is written back into xs. All threads participate (uniform control flow).
__device__ __noinline__ void gemm_hidden(
    float* xs, const float* ys, float* ws,
    const float* __restrict__ W, const float* __restrict__ bias,
    int nk, int mode, int r0, int c0, int tid)
{
    ull acc[8][4];
#pragma unroll
    for (int i = 0; i < 8; i++)
#pragma unroll
        for (int p = 0; p < 4; p++) acc[i][p] = 0ULL;

    const int nch = nk / KC;

    // prefetch chunk 0
    float4 pre[8];
    {
        const float4* src = (const float4*)W;
#pragma unroll
        for (int j = 0; j < 8; j++) pre[j] = src[tid + j * NTHR];
        float4* dst = (float4*)ws;
#pragma unroll
        for (int j = 0; j < 8; j++) dst[tid + j * NTHR] = pre[j];
    }
    __syncthreads();

    for (int c = 0; c < nch; c++) {
        const float* buf = ws + (c & 1) * (KC * HID);
        if (c + 1 < nch) {
            const float4* src = (const float4*)(W + (size_t)(c + 1) * KC * HID);
#pragma unroll
            for (int j = 0; j < 8; j++) pre[j] = src[tid + j * NTHR];
        }
        const float* xbase = xs + c * KC;
#pragma unroll
        for (int k4 = 0; k4 < KC / 4; k4++) {
            float4 a[8];
#pragma unroll
            for (int i = 0; i < 8; i++)
                a[i] = *(const float4*)(xbase + (r0 + i) * HID + k4 * 4);
#pragma unroll
            for (int kk = 0; kk < 4; kk++) {
                const float* wr = buf + (k4 * 4 + kk) * HID + c0;
                ulonglong2 b01 = *(const ulonglong2*)wr;        // (w0,w1),(w2,w3)
                ulonglong2 b23 = *(const ulonglong2*)(wr + 4);  // (w4,w5),(w6,w7)
#pragma unroll
                for (int i = 0; i < 8; i++) {
                    float av = (kk == 0) ? a[i].x : (kk == 1) ? a[i].y
                             : (kk == 2) ? a[i].z : a[i].w;
                    ull A2 = pk2(av, av);
                    fma2(acc[i][0], A2, b01.x);
                    fma2(acc[i][1], A2, b01.y);
                    fma2(acc[i][2], A2, b23.x);
                    fma2(acc[i][3], A2, b23.y);
                }
            }
        }
        if (c + 1 < nch) {
            float4* dst = (float4*)(ws + ((c + 1) & 1) * (KC * HID));
#pragma unroll
            for (int j = 0; j < 8; j++) dst[tid + j * NTHR] = pre[j];
        }
        __syncthreads();
    }

    // epilogue: bias + activation, write back to xs
    float4 bv0 = *(const float4*)(bias + c0);
    float4 bv1 = *(const float4*)(bias + c0 + 4);
    float bb[8] = {bv0.x, bv0.y, bv0.z, bv0.w, bv1.x, bv1.y, bv1.z, bv1.w};
#pragma unroll
    for (int i = 0; i < 8; i++) {
        float v[8];
#pragma unroll
        for (int p = 0; p < 4; p++) upk2(acc[i][p], v[2 * p], v[2 * p + 1]);
#pragma unroll
        for (int j = 0; j < 8; j++) v[j] += bb[j];
        if (mode == 1) {
#pragma unroll
            for (int j = 0; j < 8; j++) v[j] = fmaxf(v[j], 0.0f);
        } else if (mode == 2) {
            const float* yr = ys + (r0 + i) * HID + c0;
            float4 y0 = *(const float4*)yr;
            float4 y1 = *(const float4*)(yr + 4);
            v[0] = y0.x - v[0]; v[1] = y0.y - v[1];
            v[2] = y0.z - v[2]; v[3] = y0.w - v[3];
            v[4] = y1.x - v[4]; v[5] = y1.y - v[5];
            v[6] = y1.z - v[6]; v[7] = y1.w - v[7];
        }
        float* xr = xs + (r0 + i) * HID + c0;
        *(float4*)xr       = make_float4(v[0], v[1], v[2], v[3]);
        *(float4*)(xr + 4) = make_float4(v[4], v[5], v[6], v[7]);
    }
    __syncthreads();
}

// Final GEMM: out[TM x ODIM] = xs[TM x HID] @ W[HID x ODIM] + bias, to global.
__device__ __noinline__ void gemm_final(
    const float* xs, float* ws,
    const float* __restrict__ W, const float* __restrict__ bias,
    float* __restrict__ out, int row_base, int r0, int lane, int tid)
{
    ull acc[8][2];
#pragma unroll
    for (int i = 0; i < 8; i++) { acc[i][0] = 0ULL; acc[i][1] = 0ULL; }

    const int c0 = lane * 4;
    const int nch = HID / KC;  // 8

    float4 pre[4];
    {
        const float4* src = (const float4*)W;
#pragma unroll
        for (int j = 0; j < 4; j++) pre[j] = src[tid + j * NTHR];
        float4* dst = (float4*)ws;
#pragma unroll
        for (int j = 0; j < 4; j++) dst[tid + j * NTHR] = pre[j];
    }
    __syncthreads();

    for (int c = 0; c < nch; c++) {
        const float* buf = ws + (c & 1) * (KC * ODIM);
        if (c + 1 < nch) {
            const float4* src = (const float4*)(W + (size_t)(c + 1) * KC * ODIM);
#pragma unroll
            for (int j = 0; j < 4; j++) pre[j] = src[tid + j * NTHR];
        }
        const float* xbase = xs + c * KC;
#pragma unroll
        for (int k4 = 0; k4 < KC / 4; k4++) {
            float4 a[8];
#pragma unroll
            for (int i = 0; i < 8; i++)
                a[i] = *(const float4*)(xbase + (r0 + i) * HID + k4 * 4);
#pragma unroll
            for (int kk = 0; kk < 4; kk++) {
                const float* wr = buf + (k4 * 4 + kk) * ODIM + c0;
                ulonglong2 b01 = *(const ulonglong2*)wr;
#pragma unroll
                for (int i = 0; i < 8; i++) {
                    float av = (kk == 0) ? a[i].x : (kk == 1) ? a[i].y
                             : (kk == 2) ? a[i].z : a[i].w;
                    ull A2 = pk2(av, av);
                    fma2(acc[i][0], A2, b01.x);
                    fma2(acc[i][1], A2, b01.y);
                }
            }
        }
        if (c + 1 < nch) {
            float4* dst = (float4*)(ws + ((c + 1) & 1) * (KC * ODIM));
#pragma unroll
            for (int j = 0; j < 4; j++) dst[tid + j * NTHR] = pre[j];
        }
        __syncthreads();
    }

    float4 bv = *(const float4*)(bias + c0);
#pragma unroll
    for (int i = 0; i < 8; i++) {
        float v0, v1, v2, v3;
        upk2(acc[i][0], v0, v1);
        upk2(acc[i][1], v2, v3);
        v0 += bv.x; v1 += bv.y; v2 += bv.z; v3 += bv.w;
        *(float4*)(out + (size_t)(row_base + r0 + i) * ODIM + c0)
            = make_float4(v0, v1, v2, v3);
    }
}

__global__ void __launch_bounds__(NTHR, 1)
inv_resnet_kernel(
    const float* __restrict__ x,
    const float* __restrict__ W_init, const float* __restrict__ b_init,
    const float* __restrict__ Wg1,    const float* __restrict__ bg1,
    const float* __restrict__ Wg2,    const float* __restrict__ bg2,
    const float* __restrict__ W_final, const float* __restrict__ b_final,
    float* __restrict__ out)
{
    extern __shared__ float sm[];
    float* xs = sm;                 // [TM][HID] current state (A operand + result)
    float* ys = sm + TM * HID;      // [TM][HID] block input y
    float* ws = sm + 2 * TM * HID;  // [2][KC][HID] weight double buffer

    const int tid  = threadIdx.x;
    const int lane = tid & 31;
    const int wrp  = tid >> 5;
    const int r0   = wrp * 8;       // 8 rows per thread (warp = row group)
    const int c0   = lane * 8;      // 8 cols per thread (lane = col group)
    const int row_base = blockIdx.x * TM;

    // Load x tile [TM x LAT] into xs (row stride HID)
    {
        const int nf4 = TM * LAT / 4;  // 2048
        for (int i = tid; i < nf4; i += NTHR) {
            int r  = i >> 5;           // LAT/4 = 32 float4 per row
            int c4 = i & 31;
            float4 v = ((const float4*)(x + (size_t)(row_base + r) * LAT))[c4];
            *(float4*)(xs + r * HID + c4 * 4) = v;
        }
    }
    __syncthreads();

    // h = x @ W_init + b_init
    gemm_hidden(xs, ys, ws, W_init, b_init, LAT, 0, r0, c0, tid);

    for (int b = 0; b < NBLK; b++) {
        // y = h (copy xs -> ys); x starts at y
#pragma unroll
        for (int j = 0; j < (TM * HID / 4) / NTHR; j++)
            ((float4*)ys)[tid + j * NTHR] = ((const float4*)xs)[tid + j * NTHR];
        __syncthreads();

        const float* W1 = Wg1 + (size_t)b * HID * HID;
        const float* W2 = Wg2 + (size_t)b * HID * HID;
        const float* b1 = bg1 + b * HID;
        const float* b2 = bg2 + b * HID;

        for (int it = 0; it < NIT; it++) {
            gemm_hidden(xs, ys, ws, W1, b1, HID, 1, r0, c0, tid);  // t = relu(x@W1+b1)
            gemm_hidden(xs, ys, ws, W2, b2, HID, 2, r0, c0, tid);  // x = y - (t@W2+b2)
        }
    }

    // out = h @ W_final + b_final
    gemm_final(xs, ws, W_final, b_final, out, row_base, r0, lane, tid);
}

extern "C" void kernel_launch(void* const* d_in, const int* in_sizes, int n_in,
                              void* d_out, int out_size)
{
    const float* x       = (const float*)d_in[0];
    const float* W_init  = (const float*)d_in[1];
    const float* b_init  = (const float*)d_in[2];
    const float* Wg1     = (const float*)d_in[3];
    const float* bg1     = (const float*)d_in[4];
    const float* Wg2     = (const float*)d_in[5];
    const float* bg2     = (const float*)d_in[6];
    const float* W_final = (const float*)d_in[7];
    const float* b_final = (const float*)d_in[8];
    float* out = (float*)d_out;

    const int batch = in_sizes[0] / LAT;

    cudaFuncSetAttribute(inv_resnet_kernel,
                         cudaFuncAttributeMaxDynamicSharedMemorySize, SMEM_BYTES);

    dim3 grid(batch / TM);
    inv_resnet_kernel<<<grid, NTHR, SMEM_BYTES>>>(
        x, W_init, b_init, Wg1, bg1, Wg2, bg2, W_final, b_final, out);
}

// round 5
// speedup vs baseline: 4.9604x; 4.9604x over previous
#include <cuda_runtime.h>
#include <cuda_bf16.h>
#include <cstdint>

#define HID   256
#define LAT   128
#define ODIM  128
#define NBLK  4
#define NIT   10
#define TM    128
#define NTHR  256
#define KC    32

// ---------------- SMEM layout (bytes) ----------------
#define SM_AHI   1024
#define SM_ALO   (1024 + 65536)
#define SM_B     (1024 + 2 * 65536)          // 132096
#define B_STG_H  32768                       // hidden GEMM stage (N=256)
#define B_STG_F  16384                       // final GEMM stage (N=128)
#define SM_BYTES (SM_B + 2 * B_STG_H)        // 197632
// control region: [0] tmem ptr, [16],[24] mbarriers

// ---------------- pre-processed weight blob ----------------
// layout per matrix: stages of KC=32 K; each stage is the exact SMEM image:
// N rows x 128B; bytes [0,64) = bf16 hi of 32 K, [64,128) = bf16 lo; SW128 swizzled.
#define WB_INIT  0u
#define WB_G1(b) (131072u + (unsigned)(b) * 262144u)
#define WB_G2(b) (1179648u + (unsigned)(b) * 262144u)
#define WB_FIN   2228224u
__device__ __align__(128) unsigned char g_wblob[2359296];

#define IDESC_N256 0x8400490u   // f32 acc, bf16 x bf16, M=128, N=256
#define IDESC_N128 0x8200490u   // f32 acc, bf16 x bf16, M=128, N=128

static constexpr uint64_t DESC_BASE_SW128 =
    (uint64_t(2) << 61) | (uint64_t(1) << 46) | (uint64_t(64) << 32) | (uint64_t(1) << 16);

// tcgen05 is arch-SPECIFIC (sm_103a): the harness also runs a compute_103
// (family) ptxas pass which rejects it. Gate every tcgen05 instruction on the
// arch-specific feature macros; the base pass gets stubs that never execute
// (the fatbin's exact-match sm_103a SASS is what runs on the GB300).
#if defined(__CUDA_ARCH__) && \
    (defined(__CUDA_ARCH_FEAT_SM103_ALL) || defined(__CUDA_ARCH_FEAT_SM100_ALL) || \
     defined(__CUDA_ARCH_FEAT_SM101_ALL) || defined(__CUDA_ARCH_SPECIFIC__))
#define TC_OK 1
#else
#define TC_OK 0
#endif

// ---------------- PTX helpers ----------------
static __device__ __forceinline__ uint32_t smem_u32(const void* p) {
    uint32_t a;
    asm("{ .reg .u64 t; cvta.to.shared.u64 t, %1; cvt.u32.u64 %0, t; }" : "=r"(a) : "l"(p));
    return a;
}
static __device__ __forceinline__ uint32_t elect1() {
    uint32_t p;
    asm volatile("{ .reg .pred p; elect.sync _|p, 0xFFFFFFFF; selp.b32 %0, 1, 0, p; }" : "=r"(p));
    return p;
}
static __device__ __forceinline__ uint64_t mk_desc(uint32_t addr) {
    return DESC_BASE_SW128 | ((uint64_t)(addr >> 4) & 0x3FFF);
}

#if TC_OK
static __device__ __forceinline__ void mma_ss(uint32_t d, uint64_t ad, uint64_t bd,
                                              uint32_t idesc, uint32_t en) {
    asm volatile(
        "{\n\t.reg .pred p;\n\tsetp.ne.u32 p, %4, 0;\n\t"
        "tcgen05.mma.cta_group::1.kind::f16 [%0], %1, %2, %3, {%5, %5, %5, %5}, p;\n\t}"
        :: "r"(d), "l"(ad), "l"(bd), "r"(idesc), "r"(en), "r"(0u) : "memory");
}
#define TC_COMMIT(mb) \
    asm volatile("tcgen05.commit.cta_group::1.mbarrier::arrive::one.shared::cluster.b64 [%0];" \
                 :: "r"(mb) : "memory")
#define TC_FENCE_AFTER()   asm volatile("tcgen05.fence::after_thread_sync;" ::: "memory")
#define TC_FENCE_BEFORE()  asm volatile("tcgen05.fence::before_thread_sync;" ::: "memory")
#define TC_WAIT_LD()   asm volatile("tcgen05.wait::ld.sync.aligned;" ::: "memory")
#define TC_WAIT_ST()   asm volatile("tcgen05.wait::st.sync.aligned;" ::: "memory")
#define TC_ALLOC(sa, n) \
    asm volatile("tcgen05.alloc.cta_group::1.sync.aligned.shared::cta.b32 [%0], %1;" \
                 :: "r"(sa), "r"((uint32_t)(n)) : "memory")
#define TC_DEALLOC(t, n) \
    asm volatile("tcgen05.dealloc.cta_group::1.sync.aligned.b32 %0, %1;" :: "r"(t), "r"((uint32_t)(n)))
#define TC_RELINQ() \
    asm volatile("tcgen05.relinquish_alloc_permit.cta_group::1.sync.aligned;")

#define LDTM32(r, a)                                                                    \
    asm volatile("tcgen05.ld.sync.aligned.32x32b.x32.b32 "                              \
        "{%0,%1,%2,%3,%4,%5,%6,%7,%8,%9,%10,%11,%12,%13,%14,%15,"                       \
        "%16,%17,%18,%19,%20,%21,%22,%23,%24,%25,%26,%27,%28,%29,%30,%31}, [%32];"      \
        : "=r"((r)[0]),"=r"((r)[1]),"=r"((r)[2]),"=r"((r)[3]),"=r"((r)[4]),"=r"((r)[5]),\
          "=r"((r)[6]),"=r"((r)[7]),"=r"((r)[8]),"=r"((r)[9]),"=r"((r)[10]),"=r"((r)[11]),\
          "=r"((r)[12]),"=r"((r)[13]),"=r"((r)[14]),"=r"((r)[15]),"=r"((r)[16]),"=r"((r)[17]),\
          "=r"((r)[18]),"=r"((r)[19]),"=r"((r)[20]),"=r"((r)[21]),"=r"((r)[22]),"=r"((r)[23]),\
          "=r"((r)[24]),"=r"((r)[25]),"=r"((r)[26]),"=r"((r)[27]),"=r"((r)[28]),"=r"((r)[29]),\
          "=r"((r)[30]),"=r"((r)[31]) : "r"(a))

#define STTM32(a, r)                                                                    \
    asm volatile("tcgen05.st.sync.aligned.32x32b.x32.b32 [%0], "                        \
        "{%1,%2,%3,%4,%5,%6,%7,%8,%9,%10,%11,%12,%13,%14,%15,%16,"                      \
        "%17,%18,%19,%20,%21,%22,%23,%24,%25,%26,%27,%28,%29,%30,%31,%32};"             \
        :: "r"(a), "r"((r)[0]),"r"((r)[1]),"r"((r)[2]),"r"((r)[3]),"r"((r)[4]),"r"((r)[5]),\
           "r"((r)[6]),"r"((r)[7]),"r"((r)[8]),"r"((r)[9]),"r"((r)[10]),"r"((r)[11]),   \
           "r"((r)[12]),"r"((r)[13]),"r"((r)[14]),"r"((r)[15]),"r"((r)[16]),"r"((r)[17]),\
           "r"((r)[18]),"r"((r)[19]),"r"((r)[20]),"r"((r)[21]),"r"((r)[22]),"r"((r)[23]),\
           "r"((r)[24]),"r"((r)[25]),"r"((r)[26]),"r"((r)[27]),"r"((r)[28]),"r"((r)[29]),\
           "r"((r)[30]),"r"((r)[31]) : "memory")
#else
// Stubs for the non-arch-specific (compute_103 family) compile pass.
// This code path never executes on the GB300 (sm_103a SASS is exact-match).
static __device__ __forceinline__ void mma_ss(uint32_t, uint64_t, uint64_t, uint32_t, uint32_t) {}
#define TC_COMMIT(mb)      do { (void)(mb); } while (0)
#define TC_FENCE_AFTER()   do {} while (0)
#define TC_FENCE_BEFORE()  do {} while (0)
#define TC_WAIT_LD()       do {} while (0)
#define TC_WAIT_ST()       do {} while (0)
#define TC_ALLOC(sa, n)    do { (void)(sa); (void)(n); } while (0)
#define TC_DEALLOC(t, n)   do { (void)(t); (void)(n); } while (0)
#define TC_RELINQ()        do {} while (0)
#define LDTM32(r, a)       do { _Pragma("unroll") for (int _i = 0; _i < 32; _i++) (r)[_i] = 0u; (void)(a); } while (0)
#define STTM32(a, r)       do { (void)(a); (void)(r); } while (0)
#endif

#define MBAR_INIT(a) \
    asm volatile("mbarrier.init.shared.b64 [%0], %1;" :: "r"(a), "r"(1u) : "memory")
#define MBAR_INVAL(a) \
    asm volatile("mbarrier.inval.shared.b64 [%0];" :: "r"(a) : "memory")
#define MBAR_WAIT(a, ph) do {                                                          \
    asm volatile("{\n\t.reg .pred P;\nWL_%=:\n\t"                                      \
        "mbarrier.try_wait.parity.acquire.cta.shared::cta.b64 P, [%0], %1, 0x989680;\n\t" \
        "@P bra.uni WD_%=;\n\tbra.uni WL_%=;\nWD_%=:\n\t}"                             \
        :: "r"(a), "r"((uint32_t)(ph)) : "memory");                                    \
} while (0)
#define FENCE_ASYNC()  asm volatile("fence.proxy.async.shared::cta;" ::: "memory")

// A-operand blocked-atom + SW128 byte address for (row m, k element)
static __device__ __forceinline__ uint32_t a_addr(int m, int k) {
    uint32_t off = (uint32_t)(((m >> 3) + (k >> 6) * 16) * 1024 + (m & 7) * 128 + (k & 63) * 2);
    return off ^ ((off >> 3) & 0x70);
}
static __device__ __forceinline__ void split_bf(float v, unsigned short& h, unsigned short& l) {
    __nv_bfloat16 hb = __float2bfloat16(v);
    float hf = __bfloat162float(hb);
    __nv_bfloat16 lb = __float2bfloat16(v - hf);
    h = *reinterpret_cast<unsigned short*>(&hb);
    l = *reinterpret_cast<unsigned short*>(&lb);
}
static __device__ __forceinline__ float bfu2f(uint32_t us) {
    return __uint_as_float((us & 0xFFFFu) << 16);
}

// ---------------- weight prep kernel ----------------
// W is [K, N] row-major fp32 (as used by h @ W). Produce stage-major SMEM images
// of B = W^T ([N, K] K-major), split hi/lo bf16, SW128 swizzled.
__global__ void prep_w(const float* __restrict__ W, int K, int N, unsigned blob_off) {
    int idx = blockIdx.x * blockDim.x + threadIdx.x;
    if (idx >= K * N) return;
    int k = idx / N, n = idx % N;
    float w = W[idx];
    unsigned short hs, ls;
    split_bf(w, hs, ls);
    int stage = k >> 5, kl = k & 31;
    unsigned row = (unsigned)((n >> 3) * 1024 + (n & 7) * 128);
    unsigned oh = row + kl * 2;
    unsigned ol = row + (32 + kl) * 2;
    oh ^= (oh >> 3) & 0x70;
    ol ^= (ol >> 3) & 0x70;
    unsigned char* sb = g_wblob + blob_off + (size_t)stage * ((size_t)N * 128);
    *(unsigned short*)(sb + oh) = hs;
    *(unsigned short*)(sb + ol) = ls;
}

// ---------------- main kernel pieces ----------------

// GEMM: D(TMEM cols 0..N) = A(hi/lo in SMEM) x B(streamed stages), 3-term split-bf16.
static __device__ void run_gemm(char* sm, uint32_t smb, uint32_t tmem,
                                const unsigned char* blob, int nst,
                                int stage_bytes, uint32_t idesc, int f4pt, int* phase) {
    const int tid = threadIdx.x;
    const int wid = tid >> 5;
    // prefill stage 0
    {
        const float4* s = (const float4*)blob;
        float4* d = (float4*)(sm + SM_B);
        for (int j = 0; j < f4pt; j++) d[tid + j * NTHR] = s[tid + j * NTHR];
    }
    FENCE_ASYNC();
    __syncthreads();

    const uint64_t ah = mk_desc(smb + SM_AHI);
    const uint64_t al = mk_desc(smb + SM_ALO);

    for (int c = 0; c < nst; c++) {
        float4 pre[8];
        if (c + 1 < nst) {
            const float4* s = (const float4*)(blob + (size_t)(c + 1) * stage_bytes);
            for (int j = 0; j < f4pt; j++) pre[j] = s[tid + j * NTHR];
        }
        if (wid == 0 && elect1()) {
            uint64_t bd = mk_desc(smb + SM_B + (uint32_t)(c & 1) * stage_bytes);
#pragma unroll
            for (int s2 = 0; s2 < 2; s2++) {
                int s = c * 2 + s2;
                uint32_t ao = (uint32_t)((s >> 2) * 1024 + (s & 3) * 2);
                uint32_t bo = (uint32_t)(s2 * 2);
                mma_ss(tmem, ah + ao, bd + bo, idesc, (uint32_t)((c | s2) != 0)); // hi*hi
                mma_ss(tmem, al + ao, bd + bo, idesc, 1u);                        // lo*hi
                mma_ss(tmem, ah + ao, bd + bo + 4, idesc, 1u);                    // hi*lo
            }
            TC_COMMIT(smb + 16 + (uint32_t)(c & 1) * 8);
        }
        if (c + 1 < nst) {
            if (c >= 1) {
                int b = (c - 1) & 1;
                MBAR_WAIT(smb + 16 + (uint32_t)b * 8, phase[b]);
                phase[b] ^= 1;
            }
            float4* d = (float4*)(sm + SM_B + (size_t)((c + 1) & 1) * stage_bytes);
            for (int j = 0; j < f4pt; j++) d[tid + j * NTHR] = pre[j];
        }
        FENCE_ASYNC();
        __syncthreads();
    }
    // drain outstanding commits (stages nst-2, nst-1)
    MBAR_WAIT(smb + 16 + 0, phase[0]); phase[0] ^= 1;
    MBAR_WAIT(smb + 16 + 8, phase[1]); phase[1] ^= 1;
}

// Epilogue for hidden GEMMs (N=256): read D, apply bias/act, split to A hi/lo.
// mode 0: v = d + b ; mode 1: v = relu(d + b) ; mode 2: v = y - (d + b)  (y in TMEM 256+)
static __device__ void epi_hidden(char* sm, uint32_t tmem, const float* __restrict__ bias, int mode) {
    const int tid = threadIdx.x, w = tid >> 5, lane = tid & 31;
    const int m = (w & 3) * 32 + lane, h = w >> 2;
    TC_FENCE_AFTER();
#pragma unroll 1
    for (int t = 0; t < 4; t++) {
        int n0 = h * 128 + t * 32;
        uint32_t d[32];
        LDTM32(d, tmem + (uint32_t)n0);
        uint32_t yv[32];
        if (mode == 2) LDTM32(yv, tmem + 256u + (uint32_t)n0);
        TC_WAIT_LD();
        float4 bq[8];
#pragma unroll
        for (int j = 0; j < 8; j++) bq[j] = ((const float4*)(bias + n0))[j];
        const float* bf = (const float*)bq;
#pragma unroll
        for (int q = 0; q < 8; q++) {
            uint32_t hp[2], lp[2];
#pragma unroll
            for (int e = 0; e < 2; e++) {
                unsigned short hs[2], ls[2];
#pragma unroll
                for (int u = 0; u < 2; u++) {
                    int r = q * 4 + e * 2 + u;
                    float v = __uint_as_float(d[r]) + bf[r];
                    if (mode == 1) v = fmaxf(v, 0.0f);
                    else if (mode == 2) v = __uint_as_float(yv[r]) - v;
                    split_bf(v, hs[u], ls[u]);
                }
                hp[e] = (uint32_t)hs[0] | ((uint32_t)hs[1] << 16);
                lp[e] = (uint32_t)ls[0] | ((uint32_t)ls[1] << 16);
            }
            uint32_t ad = a_addr(m, n0 + q * 4);
            *(uint2*)(sm + SM_AHI + ad) = make_uint2(hp[0], hp[1]);
            *(uint2*)(sm + SM_ALO + ad) = make_uint2(lp[0], lp[1]);
        }
    }
    TC_FENCE_BEFORE();
    FENCE_ASYNC();
    __syncthreads();
}

// Copy current activation (A hi+lo, fp32-reconstructed) into TMEM y (cols 256..511)
static __device__ void copy_y(char* sm, uint32_t tmem) {
    const int tid = threadIdx.x, w = tid >> 5, lane = tid & 31;
    const int m = (w & 3) * 32 + lane, h = w >> 2;
#pragma unroll 1
    for (int t = 0; t < 4; t++) {
        int n0 = h * 128 + t * 32;
        uint32_t u[32];
#pragma unroll
        for (int q = 0; q < 8; q++) {
            uint32_t ad = a_addr(m, n0 + q * 4);
            uint2 hv = *(const uint2*)(sm + SM_AHI + ad);
            uint2 lv = *(const uint2*)(sm + SM_ALO + ad);
            u[q * 4 + 0] = __float_as_uint(bfu2f(hv.x) + bfu2f(lv.x));
            u[q * 4 + 1] = __float_as_uint(bfu2f(hv.x >> 16) + bfu2f(lv.x >> 16));
            u[q * 4 + 2] = __float_as_uint(bfu2f(hv.y) + bfu2f(lv.y));
            u[q * 4 + 3] = __float_as_uint(bfu2f(hv.y >> 16) + bfu2f(lv.y >> 16));
        }
        STTM32(tmem + 256u + (uint32_t)n0, u);
    }
    TC_WAIT_ST();
    __syncthreads();
}

// Build initial A (hi/lo) from global x [TM rows x LAT]
static __device__ void build_initA(char* sm, const float* __restrict__ x, int row_base) {
    const int tid = threadIdx.x;
    const int m = tid >> 1, k0 = (tid & 1) * 64;
    const float4* xr = (const float4*)(x + (size_t)(row_base + m) * LAT + k0);
#pragma unroll
    for (int j = 0; j < 16; j++) {
        float4 v = xr[j];
        float vv[4] = {v.x, v.y, v.z, v.w};
        uint32_t hp[2], lp[2];
#pragma unroll
        for (int e = 0; e < 2; e++) {
            unsigned short hs[2], ls[2];
#pragma unroll
            for (int u = 0; u < 2; u++) split_bf(vv[e * 2 + u], hs[u], ls[u]);
            hp[e] = (uint32_t)hs[0] | ((uint32_t)hs[1] << 16);
            lp[e] = (uint32_t)ls[0] | ((uint32_t)ls[1] << 16);
        }
        uint32_t ad = a_addr(m, k0 + j * 4);
        *(uint2*)(sm + SM_AHI + ad) = make_uint2(hp[0], hp[1]);
        *(uint2*)(sm + SM_ALO + ad) = make_uint2(lp[0], lp[1]);
    }
    FENCE_ASYNC();
    __syncthreads();
}

// Final epilogue: out = D(cols 0..127) + b_final, STG fp32
static __device__ void epi_final(uint32_t tmem, const float* __restrict__ bias,
                                 float* __restrict__ out, int row_base) {
    const int tid = threadIdx.x, w = tid >> 5, lane = tid & 31;
    const int m = (w & 3) * 32 + lane, h = w >> 2;
    TC_FENCE_AFTER();
#pragma unroll 1
    for (int t = 0; t < 2; t++) {
        int n0 = h * 64 + t * 32;
        uint32_t d[32];
        LDTM32(d, tmem + (uint32_t)n0);
        TC_WAIT_LD();
        float4 bq[8];
#pragma unroll
        for (int j = 0; j < 8; j++) bq[j] = ((const float4*)(bias + n0))[j];
        const float* bf = (const float*)bq;
        float* orow = out + (size_t)(row_base + m) * ODIM + n0;
#pragma unroll
        for (int q = 0; q < 8; q++) {
            float4 o;
            o.x = __uint_as_float(d[q * 4 + 0]) + bf[q * 4 + 0];
            o.y = __uint_as_float(d[q * 4 + 1]) + bf[q * 4 + 1];
            o.z = __uint_as_float(d[q * 4 + 2]) + bf[q * 4 + 2];
            o.w = __uint_as_float(d[q * 4 + 3]) + bf[q * 4 + 3];
            *(float4*)(orow + q * 4) = o;
        }
    }
}

__global__ void __launch_bounds__(NTHR, 1)
inv_main(const float* __restrict__ x,
         const float* __restrict__ b_init, const float* __restrict__ bg1,
         const float* __restrict__ bg2,    const float* __restrict__ b_final,
         float* __restrict__ out) {
    extern __shared__ __align__(1024) char sm[];
    const uint32_t smb = smem_u32(sm);
    const int tid = threadIdx.x, wid = tid >> 5;
    const int row_base = blockIdx.x * TM;

    if (tid == 0) { MBAR_INIT(smb + 16); MBAR_INIT(smb + 24); }
    if (wid == 0) { TC_ALLOC(smb, 512); TC_RELINQ(); }
    __syncthreads();
    uint32_t tmem;
    asm volatile("ld.shared.b32 %0, [%1];" : "=r"(tmem) : "r"(smb));

    int phase[2] = {0, 0};

    build_initA(sm, x, row_base);
    // h = x @ W_init + b_init
    run_gemm(sm, smb, tmem, g_wblob + WB_INIT, LAT / KC, B_STG_H, IDESC_N256, 8, phase);
    epi_hidden(sm, tmem, b_init, 0);

    for (int b = 0; b < NBLK; b++) {
        copy_y(sm, tmem);  // y = current h
        const float* b1 = bg1 + b * HID;
        const float* b2 = bg2 + b * HID;
        for (int it = 0; it < NIT; it++) {
            run_gemm(sm, smb, tmem, g_wblob + WB_G1(b), HID / KC, B_STG_H, IDESC_N256, 8, phase);
            epi_hidden(sm, tmem, b1, 1);  // t = relu(x@W1 + b1)
            run_gemm(sm, smb, tmem, g_wblob + WB_G2(b), HID / KC, B_STG_H, IDESC_N256, 8, phase);
            epi_hidden(sm, tmem, b2, 2);  // x = y - (t@W2 + b2)
        }
    }

    // out = h @ W_final + b_final
    run_gemm(sm, smb, tmem, g_wblob + WB_FIN, HID / KC, B_STG_F, IDESC_N128, 4, phase);
    epi_final(tmem, b_final, out, row_base);

    __syncthreads();
    if (tid == 0) { MBAR_INVAL(smb + 16); MBAR_INVAL(smb + 24); }
    __syncthreads();
    if (wid == 0) { TC_DEALLOC(tmem, 512); }
}

extern "C" void kernel_launch(void* const* d_in, const int* in_sizes, int n_in,
                              void* d_out, int out_size) {
    const float* x       = (const float*)d_in[0];
    const float* W_init  = (const float*)d_in[1];
    const float* b_init  = (const float*)d_in[2];
    const float* Wg1     = (const float*)d_in[3];
    const float* bg1     = (const float*)d_in[4];
    const float* Wg2     = (const float*)d_in[5];
    const float* bg2     = (const float*)d_in[6];
    const float* W_final = (const float*)d_in[7];
    const float* b_final = (const float*)d_in[8];
    float* out = (float*)d_out;

    const int batch = in_sizes[0] / LAT;

    // weight preprocessing (cheap; runs inside the graph every replay)
    prep_w<<<(LAT * HID + 255) / 256, 256>>>(W_init, LAT, HID, WB_INIT);
    for (int b = 0; b < NBLK; b++) {
        prep_w<<<(HID * HID + 255) / 256, 256>>>(Wg1 + (size_t)b * HID * HID, HID, HID, WB_G1(b));
        prep_w<<<(HID * HID + 255) / 256, 256>>>(Wg2 + (size_t)b * HID * HID, HID, HID, WB_G2(b));
    }
    prep_w<<<(HID * ODIM + 255) / 256, 256>>>(W_final, HID, ODIM, WB_FIN);

    cudaFuncSetAttribute(inv_main, cudaFuncAttributeMaxDynamicSharedMemorySize, SM_BYTES);
    inv_main<<<batch / TM, NTHR, SM_BYTES>>>(x, b_init, bg1, bg2, b_final, out);
}